// round 15
// baseline (speedup 1.0000x reference)
#include <cuda_runtime.h>
#include <cuda_bf16.h>

#define EPS 1e-6f
#define NB 16
#define NA 10
#define NT 30
#define NP_POLY 16
#define NV 200
#define SEG_PER_POLY (NV - 1)            // 199
#define NSEG (NP_POLY * SEG_PER_POLY)    // 3184 per batch
#define NPTS_WARP 10
#define NPAIR (NPTS_WARP / 2)            // 5
#define WARPS 3
#define THREADS (WARPS * 32)             // 96
#define NBA (NB * NA)                    // 160
#define GRID (NBA * NP_POLY)             // 2560
#define NGROUP (NB * NP_POLY)            // 256 (b,p) groups

typedef unsigned long long ull;

#define ADD2(d, a, b)    asm("add.rn.f32x2 %0, %1, %2;"      : "=l"(d) : "l"(a), "l"(b))
#define MUL2(d, a, b)    asm("mul.rn.f32x2 %0, %1, %2;"      : "=l"(d) : "l"(a), "l"(b))
#define FMA2(d, a, b, c) asm("fma.rn.f32x2 %0, %1, %2, %3;"  : "=l"(d) : "l"(a), "l"(b), "l"(c))
#define PACK2(d, lo, hi) asm("mov.b64 %0, {%1, %2};"         : "=l"(d) : "f"(lo), "f"(hi))
#define UNPACK2(lo, hi, s) asm("mov.b64 {%0, %1}, %2;"       : "=f"(lo), "=f"(hi) : "l"(s))

// per-(batch,segment) tables (written by producer blocks inside main)
__device__ float4 g_segA[NB * NSEG];  // {sx, evx, evy, rcp_esq}
__device__ float4 g_segB[NB * NSEG];  // {-sx, -sy, -ey, rcp_sl}
__device__ int    g_flag[NGROUP];     // 0 -> not ready; 1 -> table published

// partial results: [ba][t][poly]
__device__ float g_md[NBA * NT * NP_POLY];
__device__ int   g_ct[NBA * NT * NP_POLY];

__device__ __forceinline__ void pdl_trigger() {
    asm volatile("griddepcontrol.launch_dependents;" ::: "memory");
}
__device__ __forceinline__ void pdl_wait() {
    asm volatile("griddepcontrol.wait;" ::: "memory");
}
__device__ __forceinline__ unsigned warp_redux_min_u32(unsigned v) {
    unsigned r;
    asm("redux.sync.min.u32 %0, %1, 0xffffffff;" : "=r"(r) : "r"(v));
    return r;
}
__device__ __forceinline__ int warp_redux_add_s32(int v) {
    int r;
    asm("redux.sync.add.s32 %0, %1, 0xffffffff;" : "=r"(r) : "r"(v));
    return r;
}
__device__ __forceinline__ void st_release_gpu(int* p, int v) {
    asm volatile("st.release.gpu.global.s32 [%0], %1;" :: "l"(p), "r"(v) : "memory");
}
__device__ __forceinline__ int ld_acquire_gpu(const int* p) {
    int v;
    asm volatile("ld.acquire.gpu.global.s32 %0, [%1];" : "=r"(v) : "l"(p) : "memory");
    return v;
}

__global__ __launch_bounds__(THREADS)
void offroad_main_kernel(const float* __restrict__ points,
                         const float* __restrict__ polys) {
    int bx = blockIdx.x;
    int p  = bx & (NP_POLY - 1);
    int ba = bx >> 4;                    // b*NA + a
    int b  = ba / NA;
    int a  = ba - b * NA;
    int fp = b * NP_POLY + p;            // group id

    int tid = threadIdx.x;
    int wid = tid >> 5;
    int ln  = tid & 31;
    int t0  = wid * NPTS_WARP;

    // ---- load points first (independent of table) ----
    ull  px2[NPAIR], py2[NPAIR];
    float qx[NPTS_WARP];
    float md[NPTS_WARP];
    int   ct[NPTS_WARP];
    const float2* pts2 = (const float2*)points;
#pragma unroll
    for (int j = 0; j < NPAIR; j++) {
        float2 p0 = pts2[ba * NT + t0 + 2 * j];
        float2 p1 = pts2[ba * NT + t0 + 2 * j + 1];
        PACK2(px2[j], p0.x, p1.x);
        PACK2(py2[j], p0.y, p1.y);
        qx[2 * j] = p0.x; qx[2 * j + 1] = p1.x;
    }
#pragma unroll
    for (int k = 0; k < NPTS_WARP; k++) { md[k] = 3.4e38f; ct[k] = 0; }

    int segbase = b * NSEG + p * SEG_PER_POLY;

    if (a == 0) {
        // ---- producer: build this (b,p) table once, publish with release ----
        const float2* pv = (const float2*)polys + ((size_t)fp) * NV;
        for (int i = tid; i < SEG_PER_POLY; i += THREADS) {
            float2 v0 = pv[i];
            float2 v1 = pv[i + 1];
            float sx = v0.x, sy = v0.y, ey = v1.y;
            float evx = v1.x - sx;                 // same IEEE subs as reference
            float evy = ey - sy;
            float esq = fmaf(evx, evx, evy * evy);
            float rcp_esq = 1.0f / (esq + EPS);    // exact IEEE
            float slope   = evy / (evx + EPS);
            float rcp_sl  = 1.0f / (slope + EPS);
            g_segA[segbase + i] = make_float4(sx, evx, evy, rcp_esq);
            g_segB[segbase + i] = make_float4(-sx, -sy, -ey, rcp_sl);
        }
        __syncthreads();
        if (tid == 0) st_release_gpu(&g_flag[fp], 1);
    } else {
        // ---- consumer: acquire-poll (no fence -> no L1 invalidate) ----
        if (tid == 0) {
            while (ld_acquire_gpu(&g_flag[fp]) == 0) __nanosleep(64);
        }
        __syncthreads();
    }

    const float4* sA = g_segA + segbase;
    const float4* sB = g_segB + segbase;

#pragma unroll 1
    for (int s = ln; s < SEG_PER_POLY; s += 32) {
        float4 av = sA[s];               // {sx, evx, evy, rcp_esq} (coherent LDG)
        float4 n  = sB[s];               // {-sx, -sy, -ey, rcp_sl}

        ull nsx2, nsy2, evx2, evy2, nevx2, nevy2, ney2, c12, sx2;
        float nevx = -av.y, nevy = -av.z;
        PACK2(nsx2,  n.x, n.x);   PACK2(nsy2,  n.y, n.y);
        PACK2(evx2,  av.y, av.y); PACK2(evy2,  av.z, av.z);
        PACK2(nevx2, nevx, nevx); PACK2(nevy2, nevy, nevy);
        PACK2(ney2,  n.z, n.z);
        PACK2(c12,   n.w, n.w);   PACK2(sx2,  av.x, av.x);

#pragma unroll
        for (int j = 0; j < NPAIR; j++) {
            ull v1x2, v1y2, tt, dot2, pr2, dx2, dy2, t2, dd2, wy2, ix2;
            ADD2(v1x2, px2[j], nsx2);                 // px - sx
            ADD2(v1y2, py2[j], nsy2);                 // py - sy
            MUL2(tt, v1y2, evy2);
            FMA2(dot2, v1x2, evx2, tt);               // dot
            float d0, d1;
            UNPACK2(d0, d1, dot2);
            float pj0 = __saturatef(d0 * av.w);
            float pj1 = __saturatef(d1 * av.w);
            PACK2(pr2, pj0, pj1);
            FMA2(dx2, nevx2, pr2, v1x2);              // v1x - evx*proj
            FMA2(dy2, nevy2, pr2, v1y2);
            MUL2(t2, dy2, dy2);
            FMA2(dd2, dx2, dx2, t2);                  // d2
            float e0, e1;
            UNPACK2(e0, e1, dd2);
            md[2 * j]     = fminf(md[2 * j],     e0);
            md[2 * j + 1] = fminf(md[2 * j + 1], e1);

            // cond_y via packed sign XOR (decision-exact); ix exact scalar form
            ADD2(wy2, py2[j], ney2);                  // py - ey
            FMA2(ix2, v1y2, c12, sx2);                // sx + (py-sy)*rcp_sl
            ull xs = v1y2 ^ wy2;
            bool cy0 = ((int)(unsigned)xs) < 0;       // low-half sign differs
            bool cy1 = ((long long)xs) < 0;           // high-half sign differs
            float ix0, ix1;
            UNPACK2(ix0, ix1, ix2);
            ct[2 * j]     += (cy0 & (ix0 > qx[2 * j]))     ? 1 : 0;
            ct[2 * j + 1] += (cy1 & (ix1 > qx[2 * j + 1])) ? 1 : 0;
        }
    }

    // warp fold via redux, plain partial stores (proven deterministic path)
#pragma unroll
    for (int k = 0; k < NPTS_WARP; k++) {
        unsigned mb = warp_redux_min_u32(__float_as_uint(md[k]));
        int      cc = warp_redux_add_s32(ct[k]);
        if (ln == 0) {
            int idx = (ba * NT + t0 + k) * NP_POLY + p;
            g_md[idx] = __uint_as_float(mb);
            g_ct[idx] = cc;
        }
    }

    __syncthreads();
    pdl_trigger();
}

__global__ __launch_bounds__(32)
void reduce_kernel(float* __restrict__ out) {
    int ba = blockIdx.x;
    int t  = threadIdx.x;

    pdl_wait();

    // reset producer flags for the next graph replay (main fully done by now)
    if (ba < 128 && t < 2) g_flag[ba * 2 + t] = 0;

    float loss = 0.0f;
    if (t < NT) {
        float md = 3.4e38f;
        int ct = 0;
        const float4* pm = (const float4*)(g_md + (ba * NT + t) * NP_POLY);
        const int4*   pc = (const int4*)  (g_ct + (ba * NT + t) * NP_POLY);
#pragma unroll
        for (int q = 0; q < NP_POLY / 4; q++) {
            float4 mv = pm[q];
            int4   cv = pc[q];
            md = fminf(md, fminf(fminf(mv.x, mv.y), fminf(mv.z, mv.w)));
            ct += cv.x + cv.y + cv.z + cv.w;
        }
        float d = sqrtf(fmaxf(md, EPS));
        if (ct & 1) d = -d;
        loss = fmaxf(d + 0.5f, 0.0f);
    }
#pragma unroll
    for (int o = 16; o > 0; o >>= 1)
        loss += __shfl_xor_sync(0xffffffffu, loss, o);
    if (t == 0) out[ba] = loss;
}

extern "C" void kernel_launch(void* const* d_in, const int* in_sizes, int n_in,
                              void* d_out, int out_size) {
    const float* points = (const float*)d_in[0];  // (16,10,30,2)
    const float* polys  = (const float*)d_in[1];  // (16,16,200,2)
    float* out = (float*)d_out;                   // (16,10)

    offroad_main_kernel<<<GRID, THREADS>>>(points, polys);

    cudaLaunchAttribute attr[1];
    attr[0].id = cudaLaunchAttributeProgrammaticStreamSerialization;
    attr[0].val.programmaticStreamSerializationAllowed = 1;

    cudaLaunchConfig_t cfg_red = {};
    cfg_red.gridDim  = dim3(NBA, 1, 1);
    cfg_red.blockDim = dim3(32, 1, 1);
    cfg_red.attrs = attr;
    cfg_red.numAttrs = 1;
    cudaLaunchKernelEx(&cfg_red, reduce_kernel, out);
}

// round 17
// speedup vs baseline: 1.1014x; 1.1014x over previous
#include <cuda_runtime.h>
#include <cuda_bf16.h>
#include <cstdint>

#define EPS 1e-6f
#define NB 16
#define NA 10
#define NT 30
#define NP_POLY 16
#define NV 200
#define SEG_PER_POLY (NV - 1)            // 199
#define NSEG (NP_POLY * SEG_PER_POLY)    // 3184 per batch
#define POLYS_PER_BLK 2
#define NSEG2 (POLYS_PER_BLK * SEG_PER_POLY)   // 398 segs per block
#define CLUSTER 8                        // blocks per ba
#define NPTS_WARP 10
#define NPAIR (NPTS_WARP / 2)            // 5
#define WARPS 3
#define THREADS (WARPS * 32)             // 96
#define NBA (NB * NA)                    // 160
#define GRID (NBA * CLUSTER)             // 1280

typedef unsigned long long ull;
typedef unsigned int u32;

#define ADD2(d, a, b)    asm("add.rn.f32x2 %0, %1, %2;"      : "=l"(d) : "l"(a), "l"(b))
#define MUL2(d, a, b)    asm("mul.rn.f32x2 %0, %1, %2;"      : "=l"(d) : "l"(a), "l"(b))
#define FMA2(d, a, b, c) asm("fma.rn.f32x2 %0, %1, %2, %3;"  : "=l"(d) : "l"(a), "l"(b), "l"(c))
#define PACK2(d, lo, hi) asm("mov.b64 %0, {%1, %2};"         : "=l"(d) : "f"(lo), "f"(hi))
#define UNPACK2(lo, hi, s) asm("mov.b64 {%0, %1}, %2;"       : "=f"(lo), "=f"(hi) : "l"(s))

// per-(batch,segment) tables: two LDG.128 per segment (R14-proven shape)
__device__ float4 g_segA[NB * NSEG];  // {sx, evx, evy, rcp_esq}
__device__ float4 g_segB[NB * NSEG];  // {-sx, -sy, -ey, rcp_sl}

__device__ __forceinline__ u32 warp_redux_min_u32(u32 v) {
    u32 r;
    asm("redux.sync.min.u32 %0, %1, 0xffffffff;" : "=r"(r) : "r"(v));
    return r;
}
__device__ __forceinline__ int warp_redux_add_s32(int v) {
    int r;
    asm("redux.sync.add.s32 %0, %1, 0xffffffff;" : "=r"(r) : "r"(v));
    return r;
}
__device__ __forceinline__ u32 smem_addr_u32(const void* p) {
    u32 a;
    asm("{ .reg .u64 t; cvta.to.shared.u64 t, %1; cvt.u32.u64 %0, t; }"
        : "=r"(a) : "l"(p));
    return a;
}
__device__ __forceinline__ u32 mapa_rank0(u32 local_addr) {
    u32 r;
    asm("mapa.shared::cluster.u32 %0, %1, 0;" : "=r"(r) : "r"(local_addr));
    return r;
}
__device__ __forceinline__ void dsmem_st_u64(u32 addr, ull v) {
    asm volatile("st.shared::cluster.u64 [%0], %1;" :: "r"(addr), "l"(v) : "memory");
}

__global__ void precompute_kernel(const float* __restrict__ polys) {
    int idx = blockIdx.x * blockDim.x + threadIdx.x;
    if (idx >= NB * NSEG) return;
    int b = idx / NSEG;
    int s = idx - b * NSEG;
    int p = s / SEG_PER_POLY;
    int j = s - p * SEG_PER_POLY;
    const float* v = polys + (((size_t)b * NP_POLY + p) * NV + j) * 2;
    float sx = v[0], sy = v[1], ex = v[2], ey = v[3];
    float evx = ex - sx;                    // same IEEE subs as reference
    float evy = ey - sy;
    float esq = fmaf(evx, evx, evy * evy);
    float rcp_esq = 1.0f / (esq + EPS);     // exact IEEE
    float slope = evy / (evx + EPS);
    float rcp_sl = 1.0f / (slope + EPS);
    g_segA[idx] = make_float4(sx, evx, evy, rcp_esq);
    g_segB[idx] = make_float4(-sx, -sy, -ey, rcp_sl);
}

__global__ __launch_bounds__(THREADS) __cluster_dims__(CLUSTER, 1, 1)
void offroad_main_kernel(const float* __restrict__ points,
                         float* __restrict__ out) {
    // fold buffer (used only in rank 0's CTA): [t][rank] packed {ct, md_bits}
    __shared__ ull s_fold[NT * CLUSTER];   // 1920 B

    int bx = blockIdx.x;
    int q  = bx & (CLUSTER - 1);         // cluster rank == poly-pair id
    int ba = bx >> 3;                    // b*NA + a
    int b  = ba / NA;

    int tid = threadIdx.x;
    int wid = tid >> 5;
    int ln  = tid & 31;
    int t0  = wid * NPTS_WARP;           // 0,10,20

    ull  px2[NPAIR], py2[NPAIR];
    float qx[NPTS_WARP];
    float md[NPTS_WARP];
    int   ct[NPTS_WARP];

    const float2* pts2 = (const float2*)points;
#pragma unroll
    for (int j = 0; j < NPAIR; j++) {
        float2 p0 = pts2[ba * NT + t0 + 2 * j];
        float2 p1 = pts2[ba * NT + t0 + 2 * j + 1];
        PACK2(px2[j], p0.x, p1.x);
        PACK2(py2[j], p0.y, p1.y);
        qx[2 * j] = p0.x; qx[2 * j + 1] = p1.x;
    }
#pragma unroll
    for (int k = 0; k < NPTS_WARP; k++) { md[k] = 3.4e38f; ct[k] = 0; }

    // this block sweeps 2 polygons = 398 consecutive segments
    const float4* sA = g_segA + (b * NSEG + q * NSEG2);
    const float4* sB = g_segB + (b * NSEG + q * NSEG2);

#pragma unroll 1
    for (int s = ln; s < NSEG2; s += 32) {
        float4 av = __ldg(&sA[s]);       // {sx, evx, evy, rcp_esq}
        float4 n  = __ldg(&sB[s]);       // {-sx, -sy, -ey, rcp_sl}

        ull nsx2, nsy2, evx2, evy2, nevx2, nevy2, ney2, c12, sx2;
        float nevx = -av.y, nevy = -av.z;
        PACK2(nsx2,  n.x, n.x);   PACK2(nsy2,  n.y, n.y);
        PACK2(evx2,  av.y, av.y); PACK2(evy2,  av.z, av.z);
        PACK2(nevx2, nevx, nevx); PACK2(nevy2, nevy, nevy);
        PACK2(ney2,  n.z, n.z);
        PACK2(c12,   n.w, n.w);   PACK2(sx2,  av.x, av.x);

#pragma unroll
        for (int j = 0; j < NPAIR; j++) {
            ull v1x2, v1y2, tt, dot2, pr2, dx2, dy2, t2, dd2, wy2, ix2;
            ADD2(v1x2, px2[j], nsx2);                 // px - sx
            ADD2(v1y2, py2[j], nsy2);                 // py - sy
            MUL2(tt, v1y2, evy2);
            FMA2(dot2, v1x2, evx2, tt);               // dot
            float d0, d1;
            UNPACK2(d0, d1, dot2);
            float pj0 = __saturatef(d0 * av.w);
            float pj1 = __saturatef(d1 * av.w);
            PACK2(pr2, pj0, pj1);
            FMA2(dx2, nevx2, pr2, v1x2);              // v1x - evx*proj
            FMA2(dy2, nevy2, pr2, v1y2);
            MUL2(t2, dy2, dy2);
            FMA2(dd2, dx2, dx2, t2);                  // d2
            float e0, e1;
            UNPACK2(e0, e1, dd2);
            md[2 * j]     = fminf(md[2 * j],     e0);
            md[2 * j + 1] = fminf(md[2 * j + 1], e1);

            // cond_y via packed sign XOR (decision-exact); ix exact scalar form
            ADD2(wy2, py2[j], ney2);                  // py - ey
            FMA2(ix2, v1y2, c12, sx2);                // sx + (py-sy)*rcp_sl
            ull xs = v1y2 ^ wy2;
            bool cy0 = ((int)(unsigned)xs) < 0;
            bool cy1 = ((long long)xs) < 0;
            float ix0, ix1;
            UNPACK2(ix0, ix1, ix2);
            ct[2 * j]     += (cy0 & (ix0 > qx[2 * j]))     ? 1 : 0;
            ct[2 * j + 1] += (cy1 & (ix1 > qx[2 * j + 1])) ? 1 : 0;
        }
    }

    // warp fold (redux), then ship packed partials to rank 0's smem via DSMEM
    u32 fold_base_r0 = mapa_rank0(smem_addr_u32(s_fold));
#pragma unroll
    for (int k = 0; k < NPTS_WARP; k++) {
        u32 mb = warp_redux_min_u32(__float_as_uint(md[k]));  // bit-min == fmin (d2>=0)
        int cc = warp_redux_add_s32(ct[k]);
        if (ln == 0) {
            int slot = (t0 + k) * CLUSTER + q;
            ull v = ((ull)(u32)cc << 32) | (ull)mb;
            dsmem_st_u64(fold_base_r0 + slot * 8, v);
        }
    }

    // cluster barrier: arrive releases our DSMEM stores, wait acquires peers'
    asm volatile("barrier.cluster.arrive.aligned;" ::: "memory");
    asm volatile("barrier.cluster.wait.aligned;" ::: "memory");

    // rank 0, warp 0 finishes this ba
    if (q == 0 && wid == 0) {
        float loss = 0.0f;
        if (ln < NT) {
            u32 mb = 0xffffffffu;
            int cc = 0;
#pragma unroll
            for (int r = 0; r < CLUSTER; r++) {
                ull v = s_fold[ln * CLUSTER + r];
                u32 m = (u32)v;
                mb = (m < mb) ? m : mb;
                cc += (int)(v >> 32);
            }
            float m = __uint_as_float(mb);
            float d = sqrtf(fmaxf(m, EPS));
            if (cc & 1) d = -d;
            loss = fmaxf(d + 0.5f, 0.0f);
        }
#pragma unroll
        for (int o = 16; o > 0; o >>= 1)
            loss += __shfl_xor_sync(0xffffffffu, loss, o);
        if (ln == 0) out[ba] = loss;
    }
}

extern "C" void kernel_launch(void* const* d_in, const int* in_sizes, int n_in,
                              void* d_out, int out_size) {
    const float* points = (const float*)d_in[0];  // (16,10,30,2)
    const float* polys  = (const float*)d_in[1];  // (16,16,200,2)
    float* out = (float*)d_out;                   // (16,10)

    int total = NB * NSEG;
    precompute_kernel<<<(total + 255) / 256, 256>>>(polys);
    offroad_main_kernel<<<GRID, THREADS>>>(points, out);
}